// round 8
// baseline (speedup 1.0000x reference)
#include <cuda_runtime.h>

#define TLEN   2048
#define BATCH  8192
#define TILE   64                  // time steps per tile
#define NTILE  (TLEN / TILE)       // 32
#define BLOCKT 64                  // 2 warps; 128 blocks -> 1 block/SM
#define NBLK   (BATCH / BLOCKT)

#define IN_STRIDE   272            // 256 data + 16 pad (=16 mod 128: conflict-free, 16B-aligned)
#define OUT_STRIDE  528            // 512 data + 16 pad
#define IN_BUF_B    (3 * BLOCKT * IN_STRIDE)        // 52224 per buffer
#define OUT_BASE    (2 * IN_BUF_B)                  // 104448
#define SMEM_BYTES  (OUT_BASE + BLOCKT * OUT_STRIDE) // 138240

__device__ __forceinline__ float frcp_fast(float x) {
    float r; asm("rcp.approx.f32 %0, %1;" : "=f"(r) : "f"(x)); return r;
}
__device__ __forceinline__ float ftanh_fast(float x) {
    float r; asm("tanh.approx.f32 %0, %1;" : "=f"(r) : "f"(x)); return r;
}
__device__ __forceinline__ void cpasync16(void* dst, const void* src) {
    unsigned d = (unsigned)__cvta_generic_to_shared(dst);
    asm volatile("cp.async.cg.shared.global [%0], [%1], 16;" :: "r"(d), "l"(src) : "memory");
}
__device__ __forceinline__ void cp_commit() {
    asm volatile("cp.async.commit_group;" ::: "memory");
}
__device__ __forceinline__ void cp_wait1() {
    asm volatile("cp.async.wait_group 1;" ::: "memory");
}

extern __shared__ char smem[];

// 4 EKF steps; carried chain S@12 -> rcp@28 -> P'@32; transform off-chain.
__device__ __forceinline__ void steps4(const float4 pv, const float4 hv, const float4 sv,
                                       float& p00, float& p01, float& p11,
                                       float& x0, float& x1,
                                       float4* st)   // staging: st[0], st[1]
{
    const float zz[4] = {pv.x, pv.y, pv.z, pv.w};
    const float hh[4] = {hv.x, hv.y, hv.z, hv.w};
    const float ss[4] = {sv.x, sv.y, sv.z, sv.w};

    float4 o;
    #pragma unroll
    for (int j = 0; j < 4; j++) {
        // transform (input-only): rho = 0.75 + 0.25*tanh(5h-2.5); a = dt*rho
        const float a  = fmaf(0.25f, ftanh_fast(fmaf(5.0f, hh[j], -2.5f)), 0.75f);
        const float r  = fmaxf(100.0f * ss[j], 1.0f);
        const float q  = 0.1f * r;
        const float qs = 1.1f * r;
        const float r2 = r * r;

        // carried chain
        const float p01n = fmaf(a, p11, p01);
        const float X    = fmaf(a, p01, p00 + qs);
        const float S    = fmaf(a, p01n, X);
        const float Sinv = frcp_fast(S);               // S >= 1

        // rcp-shadow work
        const float rm   = p01n * r;
        const float n2   = p01n * p01n;
        const float p11n = p11 + q;
        const float xp0  = fmaf(a, x1, x0);
        const float y    = zz[j] - xp0;

        const float K0 = fmaf(-r, Sinv, 1.0f);
        const float K1 = p01n * Sinv;

        p00 = fmaf(-r2, Sinv, r);
        p01 = rm * Sinv;
        p11 = fmaf(-n2, Sinv, p11n);
        x0  = fmaf(K0, y, xp0);
        x1  = fmaf(K1, y, x1);

        if ((j & 1) == 0) { o.x = x0; o.y = x1; }
        else              { o.z = x0; o.w = x1; st[j >> 1] = o; }
    }
}

__global__ void __launch_bounds__(BLOCKT, 1)
ekf_kernel(const float* __restrict__ price,
           const float* __restrict__ hurst,
           const float* __restrict__ sigv,
           float* __restrict__ out)
{
    const int tid  = threadIdx.x;        // 0..63; compute role: row-in-block
    const int w    = tid >> 5;
    const int lane = tid & 31;
    const int row0 = blockIdx.x * BLOCKT;

    const float* __restrict__ srcs[3] = {price, hurst, sigv};

    // ---- coalesced tile load: warp w loads rows [w*32, w*32+32) ----
    // per input: 32 rows x 256B contiguous -> 16 LDGSTS/lane, 4 lines each
    auto issue_tile = [&](int buf, int tt) {
        #pragma unroll
        for (int inp = 0; inp < 3; inp++) {
            const float* s = srcs[inp];
            #pragma unroll
            for (int k = 0; k < 16; k++) {
                const int g = k * 32 + lane;
                const int r = w * 32 + (g >> 4);      // row in block
                const int c = g & 15;                 // 16B chunk within row-tile
                const float* src = s + (size_t)(row0 + r) * TLEN + tt * TILE + c * 4;
                char* dst = smem + buf * IN_BUF_B + (inp * BLOCKT + r) * IN_STRIDE + c * 16;
                cpasync16(dst, src);
            }
        }
        cp_commit();
    };

    // prologue: tiles 0 and 1
    issue_tile(0, 0);
    issue_tile(1, 1);
    cp_wait1();            // tile 0 resident
    __syncwarp();

    // initial state (dt=1) from tile 0, own row
    const float4 pz = *(const float4*)(smem + 0 * IN_BUF_B + (0 * BLOCKT + tid) * IN_STRIDE);
    float x0 = pz.x;
    float x1 = pz.y - pz.x;
    float p00 = 1.0f, p01 = 0.0f, p11 = 1.0f;

    #pragma unroll 1
    for (int t = 0; t < NTILE; t++) {
        const int buf = t & 1;
        const char* inP = smem + buf * IN_BUF_B + (0 * BLOCKT + tid) * IN_STRIDE;
        const char* inH = smem + buf * IN_BUF_B + (1 * BLOCKT + tid) * IN_STRIDE;
        const char* inS = smem + buf * IN_BUF_B + (2 * BLOCKT + tid) * IN_STRIDE;
        char* stRow = smem + OUT_BASE + tid * OUT_STRIDE;

        // ---- compute 64 steps, staging outputs in smem ----
        #pragma unroll 2
        for (int g4 = 0; g4 < TILE / 4; g4++) {
            const float4 pv = *(const float4*)(inP + g4 * 16);
            const float4 hv = *(const float4*)(inH + g4 * 16);
            const float4 sv = *(const float4*)(inS + g4 * 16);
            steps4(pv, hv, sv, p00, p01, p11, x0, x1,
                   (float4*)(stRow + g4 * 32));
        }

        // ---- coalesced flush: per row 512B contiguous ----
        __syncwarp();
        #pragma unroll
        for (int i = 0; i < 32; i++) {
            const int r = w * 32 + i;
            const float4 v = *(const float4*)(smem + OUT_BASE + r * OUT_STRIDE + lane * 16);
            float4* dst = (float4*)(out + (size_t)(row0 + r) * (TLEN * 2)) + t * 32 + lane;
            *dst = v;
        }
        __syncwarp();

        // ---- prefetch tile t+2 into this buffer (now free) ----
        if (t + 2 < NTILE) issue_tile(buf, t + 2);
        else               cp_commit();               // empty group keeps count uniform
        cp_wait1();                                   // tile t+1 resident
        __syncwarp();
    }
}

extern "C" void kernel_launch(void* const* d_in, const int* in_sizes, int n_in,
                              void* d_out, int out_size)
{
    const float* price = (const float*)d_in[0];
    const float* hurst = (const float*)d_in[1];
    const float* sigv  = (const float*)d_in[2];
    float* out = (float*)d_out;

    static bool attr_set = false;
    if (!attr_set) {
        cudaFuncSetAttribute(ekf_kernel, cudaFuncAttributeMaxDynamicSharedMemorySize, SMEM_BYTES);
        attr_set = true;
    }
    ekf_kernel<<<NBLK, BLOCKT, SMEM_BYTES>>>(price, hurst, sigv, out);
}